// round 16
// baseline (speedup 1.0000x reference)
#include <cuda_runtime.h>
#include <cuda_bf16.h>
#include <math.h>

#define NN 20000
#define EE 320000
#define FI 128
#define HDIM 32
#define KORD 32
#define HD2 64
#define NROWS 20096   // 157 * 128
#define SMEM_GEMM 98304

// ---------------- static device scratch ----------------
__device__ int   g_deg[NN];
__device__ float g_dis[NN];
__device__ int   g_rowcnt[NN];
__device__ int   g_rowptr[NN + 1];
__device__ int   g_rowfill[NN];
__device__ int2  g_csr[EE];                  // (src, weight bits)
__device__ __nv_bfloat16 g_Wh[2048 * 128];
__device__ __nv_bfloat16 g_Wl[2048 * 128];
__device__ __nv_bfloat16 g_Xh[(size_t)NROWS * 128];
__device__ __nv_bfloat16 g_Xl[(size_t)NROWS * 128];
__device__ float g_Y[(size_t)KORD * NN * HD2];
__device__ float g_B[3][NN * HD2];
__device__ float g_xp[NN * HDIM];
__device__ float g_asv[NN];
__device__ float g_adv[NN];
__device__ float g_u[NN];
__device__ float g_v[NN];
__device__ float g_p[HDIM];
__device__ float g_q[HDIM];
__device__ float g_cuv[2];

// ---------------- setup kernels ----------------
__global__ void k_zero() {
    int i = blockIdx.x * blockDim.x + threadIdx.x;
    int stride = gridDim.x * blockDim.x;
    for (int t = i; t < NN; t += stride) { g_deg[t] = 0; g_rowcnt[t] = 0; g_rowfill[t] = 0; }
}

__global__ void k_hist(const int* __restrict__ ei) {
    int e = blockIdx.x * blockDim.x + threadIdx.x;
    if (e >= EE) return;
    atomicAdd(&g_deg[ei[e]], 1);
    atomicAdd(&g_rowcnt[ei[EE + e]], 1);
}

__global__ void k_scan() {
    __shared__ int ssum[1024];
    int t = threadIdx.x;
    const int CH = 20;
    int base = t * CH;
    int s = 0;
    for (int i = 0; i < CH; i++) { int idx = base + i; if (idx < NN) s += g_rowcnt[idx]; }
    ssum[t] = s; __syncthreads();
    for (int off = 1; off < 1024; off <<= 1) {
        int v = (t >= off) ? ssum[t - off] : 0;
        __syncthreads();
        ssum[t] += v;
        __syncthreads();
    }
    int run = (t > 0) ? ssum[t - 1] : 0;
    for (int i = 0; i < CH; i++) {
        int idx = base + i;
        if (idx < NN) { g_rowptr[idx] = run; run += g_rowcnt[idx]; }
    }
    if (t == 1023) g_rowptr[NN] = EE;
    for (int i = 0; i < CH; i++) {
        int idx = base + i;
        if (idx < NN) {
            int d = g_deg[idx];
            g_dis[idx] = (d > 0) ? rsqrtf((float)d) : 0.f;
        }
    }
}

__global__ void k_scatter(const int* __restrict__ ei) {
    int e = blockIdx.x * blockDim.x + threadIdx.x;
    if (e >= EE) return;
    int s = ei[e], d = ei[EE + e];
    int pos = g_rowptr[d] + atomicAdd(&g_rowfill[d], 1);
    g_csr[pos] = make_int2(s, __float_as_int(-g_dis[s] * g_dis[d]));
}

__global__ void k_prep_x(const float* __restrict__ x) {
    int idx = blockIdx.x * blockDim.x + threadIdx.x;
    if (idx >= NROWS * 128) return;
    int n = idx >> 7;
    float w = (n < NN) ? x[idx] : 0.f;
    __nv_bfloat16 h = __float2bfloat16(w);
    g_Xh[idx] = h;
    g_Xl[idx] = __float2bfloat16(w - __bfloat162float(h));
}

__global__ void k_prep_wbf(const float* __restrict__ Wxz, const float* __restrict__ Wxh,
                           int n_base, int n_count) {
    int idx = blockIdx.x * blockDim.x + threadIdx.x;
    if (idx >= n_count * 128) return;
    int n = n_base + (idx >> 7), f = idx & 127;
    int k = n >> 6, j = n & 63;
    float w = (j < HDIM) ? Wxz[(k * FI + f) * HDIM + j]
                         : Wxh[(k * FI + f) * HDIM + (j - HDIM)];
    __nv_bfloat16 h = __float2bfloat16(w);
    g_Wh[(size_t)n * 128 + f] = h;
    g_Wl[(size_t)n * 128 + f] = __float2bfloat16(w - __bfloat162float(h));
}

__global__ void k_prep_pq(const float* __restrict__ Wemb, const float* __restrict__ bemb,
                          const float* __restrict__ Wcls) {
    int t = threadIdx.x;
    int i = t & 31;
    const float* wc = Wcls + ((t < 32) ? 0 : 128);
    float s = 0.f;
    for (int d = 0; d < 128; d++) s += Wemb[i * 128 + d] * wc[d];
    if (t < 32) g_p[i] = s; else g_q[i] = s;
    if (t < 2) {
        const float* w2 = Wcls + t * 128;
        float c = 0.f;
        for (int d = 0; d < 128; d++) c += bemb[d] * w2[d];
        g_cuv[t] = c;
    }
}

// ---------------- bf16 mma.sync GEMM: A tile resident, 4 cbs per block ----------------
__device__ __forceinline__ unsigned smem_u32(const void* p) {
    unsigned a;
    asm("{ .reg .u64 t; cvta.to.shared.u64 t, %1; cvt.u32.u64 %0, t; }" : "=r"(a) : "l"(p));
    return a;
}

__device__ __forceinline__ void ldsm4(unsigned* r, unsigned addr) {
    asm volatile("ldmatrix.sync.aligned.m8n8.x4.shared.b16 {%0,%1,%2,%3}, [%4];"
        : "=r"(r[0]), "=r"(r[1]), "=r"(r[2]), "=r"(r[3]) : "r"(addr));
}

__device__ __forceinline__ void mma16(float* c, const unsigned* a, unsigned b0, unsigned b1) {
    asm volatile("mma.sync.aligned.m16n8k16.row.col.f32.bf16.bf16.f32 "
        "{%0,%1,%2,%3},{%4,%5,%6,%7},{%8,%9},{%0,%1,%2,%3};"
        : "+f"(c[0]), "+f"(c[1]), "+f"(c[2]), "+f"(c[3])
        : "r"(a[0]), "r"(a[1]), "r"(a[2]), "r"(a[3]), "r"(b0), "r"(b1));
}

// grid (157, 2) per chunk; each block: A once, loop cb = cb_base + blockIdx.y*4 + it
__global__ void __launch_bounds__(256) k_gemm(int cb_base) {
    extern __shared__ unsigned char dsm[];
    unsigned char* sAh = dsm;             // 32KB: 128 rows x 256B (full K)
    unsigned char* sAl = dsm + 32768;
    unsigned char* sBh = dsm + 65536;     // 16KB: 64 rows x 256B
    unsigned char* sBl = dsm + 81920;
    unsigned bAh = smem_u32(sAh), bAl = smem_u32(sAl);
    unsigned bBh = smem_u32(sBh), bBl = smem_u32(sBl);

    int tid = threadIdx.x, wid = tid >> 5, lane = tid & 31;
    int n0 = blockIdx.x * 128;
    int m_w = (wid >> 1) * 32;
    int n_w = (wid & 1) * 32;

    // load A once: 128 rows x 16 units of 16B (hi/lo); 2 threads per row
    {
        int r = tid >> 1, h = tid & 1;
        const uint4* xh = (const uint4*)(g_Xh + (size_t)(n0 + r) * 128);
        const uint4* xl = (const uint4*)(g_Xl + (size_t)(n0 + r) * 128);
#pragma unroll
        for (int i = 0; i < 8; i++) {
            int u = h * 8 + i;
            unsigned off = (unsigned)(r * 256 + ((u ^ (r & 7)) << 4));
            *(uint4*)(sAh + off) = xh[u];
            *(uint4*)(sAl + off) = xl[u];
        }
    }
    __syncthreads();

    for (int it = 0; it < 4; it++) {
        int cb = cb_base + blockIdx.y * 4 + it;
        if (it) __syncthreads();   // all warps done reading previous B
        // load B: 64 rows x 16 units; 4 threads per row
        {
            int nr = tid >> 2, q = tid & 3;
            const uint4* wh = (const uint4*)(g_Wh + (size_t)(cb * 64 + nr) * 128);
            const uint4* wl = (const uint4*)(g_Wl + (size_t)(cb * 64 + nr) * 128);
#pragma unroll
            for (int i = 0; i < 4; i++) {
                int u = q * 4 + i;
                unsigned off = (unsigned)(nr * 256 + ((u ^ (nr & 7)) << 4));
                *(uint4*)(sBh + off) = wh[u];
                *(uint4*)(sBl + off) = wl[u];
            }
        }
        __syncthreads();

        float acc[2][4][4];
#pragma unroll
        for (int a = 0; a < 2; a++)
#pragma unroll
            for (int b = 0; b < 4; b++)
#pragma unroll
                for (int c = 0; c < 4; c++) acc[a][b][c] = 0.f;

#pragma unroll
        for (int kc = 0; kc < 2; kc++) {
#pragma unroll
            for (int s = 0; s < 4; s++) {
                int u0 = kc * 8 + s * 2;
                unsigned ah[2][4], al[2][4], bh[2][4], bl[2][4];
#pragma unroll
                for (int mt = 0; mt < 2; mt++) {
                    int rr = m_w + mt * 16 + (lane & 15);
                    int u = u0 + (lane >> 4);
                    unsigned off = (unsigned)(rr * 256 + ((u ^ (rr & 7)) << 4));
                    ldsm4(ah[mt], bAh + off);
                    ldsm4(al[mt], bAl + off);
                }
#pragma unroll
                for (int ng = 0; ng < 2; ng++) {
                    int nr = n_w + ng * 16 + (lane & 15);
                    int u = u0 + (lane >> 4);
                    unsigned off = (unsigned)(nr * 256 + ((u ^ (nr & 7)) << 4));
                    ldsm4(bh[ng], bBh + off);
                    ldsm4(bl[ng], bBl + off);
                }
#pragma unroll
                for (int mt = 0; mt < 2; mt++)
#pragma unroll
                    for (int ng = 0; ng < 2; ng++)
#pragma unroll
                        for (int hf = 0; hf < 2; hf++) {
                            float* c = acc[mt][ng * 2 + hf];
                            mma16(c, ah[mt], bh[ng][hf], bh[ng][2 + hf]);
                            mma16(c, al[mt], bh[ng][hf], bh[ng][2 + hf]);
                            mma16(c, ah[mt], bl[ng][hf], bl[ng][2 + hf]);
                        }
            }
        }

#pragma unroll
        for (int mt = 0; mt < 2; mt++)
#pragma unroll
            for (int ng = 0; ng < 2; ng++)
#pragma unroll
                for (int hf = 0; hf < 2; hf++) {
                    float* c = acc[mt][ng * 2 + hf];
                    int m0 = n0 + m_w + mt * 16 + (lane >> 2);
                    int col = n_w + ng * 16 + hf * 8 + (lane & 3) * 2;
                    if (m0 < NN)
                        *(float2*)(g_Y + ((size_t)cb * NN + m0) * HD2 + col) = make_float2(c[0], c[1]);
                    if (m0 + 8 < NN)
                        *(float2*)(g_Y + ((size_t)cb * NN + m0 + 8) * HD2 + col) = make_float2(c[2], c[3]);
                }
    }
}

// ---------------- Clenshaw step (b2 may be NULL for the first step) ----------------
__global__ void k_cheb_step(int k, float* __restrict__ bn,
                            const float* __restrict__ b1, const float* __restrict__ b2) {
    int gw = (blockIdx.x * blockDim.x + threadIdx.x) >> 5;
    int lane = threadIdx.x & 31;
    if (gw >= NN) return;
    const float* yk = g_Y + (size_t)k * NN * HD2;
    int rs = g_rowptr[gw], re = g_rowptr[gw + 1];
    int j = lane * 2;
    float ax = 0.f, ay = 0.f;
    for (int e = rs; e < re; e++) {
        int2 c = g_csr[e];
        float w = __int_as_float(c.y);
        float2 v = *(const float2*)(b1 + (size_t)c.x * HD2 + j);
        ax += w * v.x; ay += w * v.y;
    }
    float2 y = *(const float2*)(yk + (size_t)gw * HD2 + j);
    float2 p = make_float2(0.f, 0.f);
    if (b2) p = *(const float2*)(b2 + (size_t)gw * HD2 + j);
    float2 o;
    o.x = y.x + 2.f * ax - p.x;
    o.y = y.y + 2.f * ay - p.y;
    *(float2*)(bn + (size_t)gw * HD2 + j) = o;
}

// final step fused with gate + xp + attention scalars
__global__ void k_cheb_final_xp(const float* __restrict__ b1, const float* __restrict__ b2,
                                const float* __restrict__ bxz, const float* __restrict__ bhz,
                                const float* __restrict__ bxh, const float* __restrict__ bhh,
                                const float* __restrict__ Wg, const float* __restrict__ asrc,
                                const float* __restrict__ adst) {
    int gw = (blockIdx.x * blockDim.x + threadIdx.x) >> 5;
    int lane = threadIdx.x & 31;
    if (gw >= NN) return;
    int rs = g_rowptr[gw], re = g_rowptr[gw + 1];
    int j = lane * 2;
    float ax = 0.f, ay = 0.f;
    for (int e = rs; e < re; e++) {
        int2 c = g_csr[e];
        float w = __int_as_float(c.y);
        float2 v = *(const float2*)(b1 + (size_t)c.x * HD2 + j);
        ax += w * v.x; ay += w * v.y;
    }
    float2 y = *(const float2*)(g_Y + (size_t)gw * HD2 + j);
    float2 p = *(const float2*)(b2 + (size_t)gw * HD2 + j);
    float ox = y.x + ax - p.x;
    float oy = y.y + ay - p.y;
    float px = __shfl_xor_sync(0xffffffffu, ox, 16);
    float py = __shfl_xor_sync(0xffffffffu, oy, 16);
    float zx = (lane < 16) ? ox : px;
    float zy = (lane < 16) ? oy : py;
    float hx = (lane < 16) ? px : ox;
    float hy = (lane < 16) ? py : oy;
    int j0 = (lane & 15) * 2;
    float z0 = 1.f / (1.f + __expf(-(zx + bxz[j0] + bhz[j0])));
    float z1 = 1.f / (1.f + __expf(-(zy + bxz[j0 + 1] + bhz[j0 + 1])));
    float t0 = tanhf(hx + bxh[j0] + bhh[j0]);
    float t1 = tanhf(hy + bxh[j0 + 1] + bhh[j0 + 1]);
    float h0 = (1.f - z0) * t0;
    float h1 = (1.f - z1) * t1;
    float s0 = __shfl_sync(0xffffffffu, h0, lane >> 1);
    float s1 = __shfl_sync(0xffffffffu, h1, lane >> 1);
    float hval = (lane & 1) ? s1 : s0;
    float xpv = 0.f;
#pragma unroll
    for (int i = 0; i < 32; i++)
        xpv += __shfl_sync(0xffffffffu, hval, i) * Wg[i * HDIM + lane];
    g_xp[(size_t)gw * HDIM + lane] = xpv;
    float a = xpv * asrc[lane];
    float b = xpv * adst[lane];
#pragma unroll
    for (int off = 16; off; off >>= 1) {
        a += __shfl_xor_sync(0xffffffffu, a, off);
        b += __shfl_xor_sync(0xffffffffu, b, off);
    }
    if (lane == 0) { g_asv[gw] = a; g_adv[gw] = b; }
}

// ---------------- GAT: two-pass softmax, lane-batched exp ----------------
__global__ void k_gat(const float* __restrict__ bgat) {
    int gw = (blockIdx.x * blockDim.x + threadIdx.x) >> 5;
    int lane = threadIdx.x & 31;
    if (gw >= NN) return;
    float advd = g_adv[gw];
    float xpd = g_xp[(size_t)gw * HDIM + lane];
    float es = g_asv[gw] + advd;
    es = es > 0.f ? es : 0.2f * es;
    int rs = g_rowptr[gw], re = g_rowptr[gw + 1];

    float m = es;
    for (int idx = rs + lane; idx < re; idx += 32) {
        int s = g_csr[idx].x;
        float sc = g_asv[s] + advd;
        sc = sc > 0.f ? sc : 0.2f * sc;
        m = fmaxf(m, sc);
    }
#pragma unroll
    for (int off = 16; off; off >>= 1)
        m = fmaxf(m, __shfl_xor_sync(0xffffffffu, m, off));

    float wself = __expf(es - m);
    float acc = wself * xpd;
    float ssum_part = (lane == 0) ? wself : 0.f;
    for (int base = rs; base < re; base += 32) {
        int idx2 = base + lane;
        float wl = 0.f; int sl = 0;
        if (idx2 < re) {
            sl = g_csr[idx2].x;
            float sc = g_asv[sl] + advd;
            sc = sc > 0.f ? sc : 0.2f * sc;
            wl = __expf(sc - m);
        }
        ssum_part += wl;
        int n = min(32, re - base);
        for (int i = 0; i < n; i++) {
            float wi = __shfl_sync(0xffffffffu, wl, i);
            int si = __shfl_sync(0xffffffffu, sl, i);
            acc += wi * g_xp[(size_t)si * HDIM + lane];
        }
    }
    float ssum = ssum_part;
#pragma unroll
    for (int off = 16; off; off >>= 1)
        ssum += __shfl_xor_sync(0xffffffffu, ssum, off);

    float h2 = acc / ssum + bgat[lane];
    h2 = fmaxf(h2, 0.f);
    float a = h2 * g_p[lane];
    float b = h2 * g_q[lane];
#pragma unroll
    for (int off = 16; off; off >>= 1) {
        a += __shfl_xor_sync(0xffffffffu, a, off);
        b += __shfl_xor_sync(0xffffffffu, b, off);
    }
    if (lane == 0) { g_u[gw] = a + g_cuv[0]; g_v[gw] = b + g_cuv[1]; }
}

__global__ void k_out(const int* __restrict__ ei, const float* __restrict__ bcls,
                      float* __restrict__ out) {
    int e = blockIdx.x * blockDim.x + threadIdx.x;
    if (e >= EE) return;
    out[e] = g_u[ei[e]] + g_v[ei[EE + e]] + bcls[0];
}

// ---------------- launch ----------------
extern "C" void kernel_launch(void* const* d_in, const int* in_sizes, int n_in,
                              void* d_out, int out_size) {
    const float* x    = (const float*)d_in[0];
    const int*   ei   = (const int*)d_in[1];
    const float* Wxz  = (const float*)d_in[2];
    const float* Wxh  = (const float*)d_in[6];
    const float* bxz  = (const float*)d_in[8];
    const float* bhz  = (const float*)d_in[9];
    const float* bxh  = (const float*)d_in[12];
    const float* bhh  = (const float*)d_in[13];
    const float* Wgat = (const float*)d_in[14];
    const float* asrc = (const float*)d_in[15];
    const float* adst = (const float*)d_in[16];
    const float* bgat = (const float*)d_in[17];
    const float* Wemb = (const float*)d_in[18];
    const float* bemb = (const float*)d_in[19];
    const float* Wcls = (const float*)d_in[20];
    const float* bcls = (const float*)d_in[21];
    float* out = (float*)d_out;

    static cudaStream_t s2 = nullptr;
    static cudaEvent_t ev_fork = nullptr, ev_chunk[4] = {nullptr, nullptr, nullptr, nullptr};
    static float* pB = nullptr;
    static float* pY = nullptr;
    if (s2 == nullptr) {
        cudaStreamCreateWithFlags(&s2, cudaStreamNonBlocking);
        cudaEventCreateWithFlags(&ev_fork, cudaEventDisableTiming);
        for (int i = 0; i < 4; i++)
            cudaEventCreateWithFlags(&ev_chunk[i], cudaEventDisableTiming);
        cudaGetSymbolAddress((void**)&pB, g_B);
        cudaGetSymbolAddress((void**)&pY, g_Y);
        cudaFuncSetAttribute(k_gemm, cudaFuncAttributeMaxDynamicSharedMemorySize, SMEM_GEMM);
    }
    const size_t slab = (size_t)NN * HD2;
    float* buf[3] = { pB, pB + slab, pB + 2 * slab };
    float* Y31 = pY + (size_t)31 * slab;

    const int EB = (EE + 255) / 256;
    const int NB = (NN * 32 + 255) / 256;

    cudaEventRecord(ev_fork, 0);
    cudaStreamWaitEvent(s2, ev_fork, 0);

    // s2: x conversion once, then weight prep + GEMM in 4 chunks (A-reuse), descending cb
    k_prep_x<<<(NROWS * 128 + 255) / 256, 256, 0, s2>>>(x);
    for (int ch = 0; ch < 4; ch++) {
        int base = 24 - ch * 8;                 // 24, 16, 8, 0
        k_prep_wbf<<<(8 * 64 * 128 + 255) / 256, 256, 0, s2>>>(Wxz, Wxh, base * 64, 8 * 64);
        k_gemm<<<dim3(157, 2), 256, SMEM_GEMM, s2>>>(base);
        cudaEventRecord(ev_chunk[ch], s2);
    }

    // main stream: CSR build + small preps (overlaps chunk 0)
    k_zero<<<160, 256>>>();
    k_hist<<<EB, 256>>>(ei);
    k_scan<<<1, 1024>>>();
    k_scatter<<<EB, 256>>>(ei);
    k_prep_pq<<<1, 64>>>(Wemb, bemb, Wcls);

    // step chain: b31 = Y[31]; first step has b2 = NULL (b32 = 0)
    float* b1 = Y31;
    float* b2 = nullptr;
    int idx = 0;
    cudaStreamWaitEvent(0, ev_chunk[0], 0);
    for (int k = KORD - 2; k >= 1; k--) {
        if (k == 23) cudaStreamWaitEvent(0, ev_chunk[1], 0);
        if (k == 15) cudaStreamWaitEvent(0, ev_chunk[2], 0);
        if (k == 7)  cudaStreamWaitEvent(0, ev_chunk[3], 0);
        float* bn = buf[idx];
        k_cheb_step<<<NB, 256>>>(k, bn, b1, b2);
        b2 = b1; b1 = bn; idx = (idx + 1) % 3;
    }
    k_cheb_final_xp<<<NB, 256>>>(b1, b2, bxz, bhz, bxh, bhh, Wgat, asrc, adst);
    k_gat<<<NB, 256>>>(bgat);
    k_out<<<EB, 256>>>(ei, bcls, out);
}

// round 17
// speedup vs baseline: 1.0300x; 1.0300x over previous
#include <cuda_runtime.h>
#include <cuda_bf16.h>
#include <math.h>

#define NN 20000
#define EE 320000
#define FI 128
#define HDIM 32
#define KORD 32
#define HD2 64
#define NROWS 20096   // 157 * 128

// ---------------- static device scratch ----------------
__device__ int   g_deg[NN];
__device__ float g_dis[NN];
__device__ int   g_rowcnt[NN];
__device__ int   g_rowptr[NN + 1];
__device__ int   g_rowfill[NN];
__device__ int2  g_csr[EE];                  // (src, weight bits)
__device__ __nv_bfloat16 g_Wh[2048 * 128];   // weights hi, [n][f] K-major
__device__ __nv_bfloat16 g_Wl[2048 * 128];   // weights lo residual
__device__ __nv_bfloat16 g_Xh[(size_t)NROWS * 128];  // x hi
__device__ __nv_bfloat16 g_Xl[(size_t)NROWS * 128];  // x lo residual
__device__ float g_Y[(size_t)KORD * NN * HD2];
__device__ float g_B[3][NN * HD2];
__device__ float g_xp[NN * HDIM];
__device__ float g_asv[NN];
__device__ float g_adv[NN];
__device__ float g_u[NN];
__device__ float g_v[NN];
__device__ float g_p[HDIM];
__device__ float g_q[HDIM];
__device__ float g_cuv[2];

// ---------------- setup kernels ----------------
__global__ void k_zero() {
    int i = blockIdx.x * blockDim.x + threadIdx.x;
    int stride = gridDim.x * blockDim.x;
    for (int t = i; t < NN; t += stride) { g_deg[t] = 0; g_rowcnt[t] = 0; g_rowfill[t] = 0; }
}

__global__ void k_hist(const int* __restrict__ ei) {
    int e = blockIdx.x * blockDim.x + threadIdx.x;
    if (e >= EE) return;
    atomicAdd(&g_deg[ei[e]], 1);
    atomicAdd(&g_rowcnt[ei[EE + e]], 1);
}

__global__ void k_scan() {
    __shared__ int ssum[1024];
    int t = threadIdx.x;
    const int CH = 20;
    int base = t * CH;
    int s = 0;
    for (int i = 0; i < CH; i++) { int idx = base + i; if (idx < NN) s += g_rowcnt[idx]; }
    ssum[t] = s; __syncthreads();
    for (int off = 1; off < 1024; off <<= 1) {
        int v = (t >= off) ? ssum[t - off] : 0;
        __syncthreads();
        ssum[t] += v;
        __syncthreads();
    }
    int run = (t > 0) ? ssum[t - 1] : 0;
    for (int i = 0; i < CH; i++) {
        int idx = base + i;
        if (idx < NN) { g_rowptr[idx] = run; run += g_rowcnt[idx]; }
    }
    if (t == 1023) g_rowptr[NN] = EE;
    for (int i = 0; i < CH; i++) {
        int idx = base + i;
        if (idx < NN) {
            int d = g_deg[idx];
            g_dis[idx] = (d > 0) ? rsqrtf((float)d) : 0.f;
        }
    }
}

__global__ void k_scatter(const int* __restrict__ ei) {
    int e = blockIdx.x * blockDim.x + threadIdx.x;
    if (e >= EE) return;
    int s = ei[e], d = ei[EE + e];
    int pos = g_rowptr[d] + atomicAdd(&g_rowfill[d], 1);
    g_csr[pos] = make_int2(s, __float_as_int(-g_dis[s] * g_dis[d]));
}

// x -> bf16 hi/lo (rows >= NN zero-padded)
__global__ void k_prep_x(const float* __restrict__ x) {
    int idx = blockIdx.x * blockDim.x + threadIdx.x;
    if (idx >= NROWS * 128) return;
    int n = idx >> 7;
    float w = (n < NN) ? x[idx] : 0.f;
    __nv_bfloat16 h = __float2bfloat16(w);
    g_Xh[idx] = h;
    g_Xl[idx] = __float2bfloat16(w - __bfloat162float(h));
}

__global__ void k_prep_wbf(const float* __restrict__ Wxz, const float* __restrict__ Wxh,
                           int n_base, int n_count) {
    int idx = blockIdx.x * blockDim.x + threadIdx.x;
    if (idx >= n_count * 128) return;
    int n = n_base + (idx >> 7), f = idx & 127;
    int k = n >> 6, j = n & 63;
    float w = (j < HDIM) ? Wxz[(k * FI + f) * HDIM + j]
                         : Wxh[(k * FI + f) * HDIM + (j - HDIM)];
    __nv_bfloat16 h = __float2bfloat16(w);
    g_Wh[(size_t)n * 128 + f] = h;
    g_Wl[(size_t)n * 128 + f] = __float2bfloat16(w - __bfloat162float(h));
}

__global__ void k_prep_pq(const float* __restrict__ Wemb, const float* __restrict__ bemb,
                          const float* __restrict__ Wcls) {
    int t = threadIdx.x;
    int i = t & 31;
    const float* wc = Wcls + ((t < 32) ? 0 : 128);
    float s = 0.f;
    for (int d = 0; d < 128; d++) s += Wemb[i * 128 + d] * wc[d];
    if (t < 32) g_p[i] = s; else g_q[i] = s;
    if (t < 2) {
        const float* w2 = Wcls + t * 128;
        float c = 0.f;
        for (int d = 0; d < 128; d++) c += bemb[d] * w2[d];
        g_cuv[t] = c;
    }
}

// ---------------- bf16 mma.sync GEMM with ldmatrix (R15 shape) ----------------
__device__ __forceinline__ unsigned smem_u32(const void* p) {
    unsigned a;
    asm("{ .reg .u64 t; cvta.to.shared.u64 t, %1; cvt.u32.u64 %0, t; }" : "=r"(a) : "l"(p));
    return a;
}

__device__ __forceinline__ void ldsm4(unsigned* r, unsigned addr) {
    asm volatile("ldmatrix.sync.aligned.m8n8.x4.shared.b16 {%0,%1,%2,%3}, [%4];"
        : "=r"(r[0]), "=r"(r[1]), "=r"(r[2]), "=r"(r[3]) : "r"(addr));
}

__device__ __forceinline__ void mma16(float* c, const unsigned* a, unsigned b0, unsigned b1) {
    asm volatile("mma.sync.aligned.m16n8k16.row.col.f32.bf16.bf16.f32 "
        "{%0,%1,%2,%3},{%4,%5,%6,%7},{%8,%9},{%0,%1,%2,%3};"
        : "+f"(c[0]), "+f"(c[1]), "+f"(c[2]), "+f"(c[3])
        : "r"(a[0]), "r"(a[1]), "r"(a[2]), "r"(a[3]), "r"(b0), "r"(b1));
}

// grid (157, width) per chunk; cb = cb_base + blockIdx.y
__global__ void __launch_bounds__(256) k_gemm(int cb_base) {
    __shared__ __align__(16) unsigned char sAh[16384], sAl[16384];
    __shared__ __align__(16) unsigned char sBh[8192],  sBl[8192];
    unsigned bAh = smem_u32(sAh), bAl = smem_u32(sAl);
    unsigned bBh = smem_u32(sBh), bBl = smem_u32(sBl);

    int tid = threadIdx.x, wid = tid >> 5, lane = tid & 31;
    int n0 = blockIdx.x * 128;
    int cb = cb_base + blockIdx.y;
    int m_w = (wid >> 1) * 32;
    int n_w = (wid & 1) * 32;

    float acc[2][4][4];
#pragma unroll
    for (int a = 0; a < 2; a++)
#pragma unroll
        for (int b = 0; b < 4; b++)
#pragma unroll
            for (int c = 0; c < 4; c++) acc[a][b][c] = 0.f;

    for (int kc = 0; kc < 2; kc++) {
        if (kc) __syncthreads();
        // A tile: direct bf16 loads from g_Xh/g_Xl
        {
            int r = tid >> 1, h = tid & 1;
            const uint4* xh = (const uint4*)(g_Xh + (size_t)(n0 + r) * 128);
            const uint4* xl = (const uint4*)(g_Xl + (size_t)(n0 + r) * 128);
#pragma unroll
            for (int i = 0; i < 4; i++) {
                int qi = kc * 8 + h * 4 + i;
                uint4 hv = xh[qi];
                uint4 lv = xl[qi];
                int c = h * 4 + i;
                unsigned off = (unsigned)(r * 128 + ((c ^ (r & 7)) << 4));
                *(uint4*)(sAh + off) = hv;
                *(uint4*)(sAl + off) = lv;
            }
        }
        // B tile
        {
            int nr = tid >> 2, q = tid & 3;
            size_t src = (size_t)(cb * 64 + nr) * 128 + kc * 64;
#pragma unroll
            for (int i = 0; i < 2; i++) {
                int c = q * 2 + i;
                uint4 hv = *(const uint4*)(g_Wh + src + c * 8);
                uint4 lv = *(const uint4*)(g_Wl + src + c * 8);
                unsigned off = (unsigned)(nr * 128 + ((c ^ (nr & 7)) << 4));
                *(uint4*)(sBh + off) = hv;
                *(uint4*)(sBl + off) = lv;
            }
        }
        __syncthreads();

#pragma unroll
        for (int s = 0; s < 4; s++) {
            int c0 = s * 2;
            unsigned ah[2][4], al[2][4], bh[2][4], bl[2][4];
#pragma unroll
            for (int mt = 0; mt < 2; mt++) {
                int rr = m_w + mt * 16 + (lane & 15);
                int c = c0 + (lane >> 4);
                unsigned off = (unsigned)(rr * 128 + ((c ^ (rr & 7)) << 4));
                ldsm4(ah[mt], bAh + off);
                ldsm4(al[mt], bAl + off);
            }
#pragma unroll
            for (int ng = 0; ng < 2; ng++) {
                int nr = n_w + ng * 16 + (lane & 15);
                int c = c0 + (lane >> 4);
                unsigned off = (unsigned)(nr * 128 + ((c ^ (nr & 7)) << 4));
                ldsm4(bh[ng], bBh + off);
                ldsm4(bl[ng], bBl + off);
            }
#pragma unroll
            for (int mt = 0; mt < 2; mt++)
#pragma unroll
                for (int ng = 0; ng < 2; ng++)
#pragma unroll
                    for (int hf = 0; hf < 2; hf++) {
                        float* c = acc[mt][ng * 2 + hf];
                        mma16(c, ah[mt], bh[ng][hf], bh[ng][2 + hf]);
                        mma16(c, al[mt], bh[ng][hf], bh[ng][2 + hf]);
                        mma16(c, ah[mt], bl[ng][hf], bl[ng][2 + hf]);
                    }
        }
    }

#pragma unroll
    for (int mt = 0; mt < 2; mt++)
#pragma unroll
        for (int ng = 0; ng < 2; ng++)
#pragma unroll
            for (int hf = 0; hf < 2; hf++) {
                float* c = acc[mt][ng * 2 + hf];
                int m0 = n0 + m_w + mt * 16 + (lane >> 2);
                int col = n_w + ng * 16 + hf * 8 + (lane & 3) * 2;
                if (m0 < NN)
                    *(float2*)(g_Y + ((size_t)cb * NN + m0) * HD2 + col) = make_float2(c[0], c[1]);
                if (m0 + 8 < NN)
                    *(float2*)(g_Y + ((size_t)cb * NN + m0 + 8) * HD2 + col) = make_float2(c[2], c[3]);
            }
}

// ---------------- Clenshaw step (b2 may be NULL for the first step) ----------------
__global__ void k_cheb_step(int k, float* __restrict__ bn,
                            const float* __restrict__ b1, const float* __restrict__ b2) {
    int gw = (blockIdx.x * blockDim.x + threadIdx.x) >> 5;
    int lane = threadIdx.x & 31;
    if (gw >= NN) return;
    const float* yk = g_Y + (size_t)k * NN * HD2;
    int rs = g_rowptr[gw], re = g_rowptr[gw + 1];
    int j = lane * 2;
    float ax = 0.f, ay = 0.f;
    for (int e = rs; e < re; e++) {
        int2 c = g_csr[e];
        float w = __int_as_float(c.y);
        float2 v = *(const float2*)(b1 + (size_t)c.x * HD2 + j);
        ax += w * v.x; ay += w * v.y;
    }
    float2 y = *(const float2*)(yk + (size_t)gw * HD2 + j);
    float2 p = make_float2(0.f, 0.f);
    if (b2) p = *(const float2*)(b2 + (size_t)gw * HD2 + j);
    float2 o;
    o.x = y.x + 2.f * ax - p.x;
    o.y = y.y + 2.f * ay - p.y;
    *(float2*)(bn + (size_t)gw * HD2 + j) = o;
}

// final step fused with gate + xp + attention scalars
__global__ void k_cheb_final_xp(const float* __restrict__ b1, const float* __restrict__ b2,
                                const float* __restrict__ bxz, const float* __restrict__ bhz,
                                const float* __restrict__ bxh, const float* __restrict__ bhh,
                                const float* __restrict__ Wg, const float* __restrict__ asrc,
                                const float* __restrict__ adst) {
    int gw = (blockIdx.x * blockDim.x + threadIdx.x) >> 5;
    int lane = threadIdx.x & 31;
    if (gw >= NN) return;
    int rs = g_rowptr[gw], re = g_rowptr[gw + 1];
    int j = lane * 2;
    float ax = 0.f, ay = 0.f;
    for (int e = rs; e < re; e++) {
        int2 c = g_csr[e];
        float w = __int_as_float(c.y);
        float2 v = *(const float2*)(b1 + (size_t)c.x * HD2 + j);
        ax += w * v.x; ay += w * v.y;
    }
    float2 y = *(const float2*)(g_Y + (size_t)gw * HD2 + j);
    float2 p = *(const float2*)(b2 + (size_t)gw * HD2 + j);
    float ox = y.x + ax - p.x;
    float oy = y.y + ay - p.y;
    float px = __shfl_xor_sync(0xffffffffu, ox, 16);
    float py = __shfl_xor_sync(0xffffffffu, oy, 16);
    float zx = (lane < 16) ? ox : px;
    float zy = (lane < 16) ? oy : py;
    float hx = (lane < 16) ? px : ox;
    float hy = (lane < 16) ? py : oy;
    int j0 = (lane & 15) * 2;
    float z0 = 1.f / (1.f + __expf(-(zx + bxz[j0] + bhz[j0])));
    float z1 = 1.f / (1.f + __expf(-(zy + bxz[j0 + 1] + bhz[j0 + 1])));
    float t0 = tanhf(hx + bxh[j0] + bhh[j0]);
    float t1 = tanhf(hy + bxh[j0 + 1] + bhh[j0 + 1]);
    float h0 = (1.f - z0) * t0;
    float h1 = (1.f - z1) * t1;
    float s0 = __shfl_sync(0xffffffffu, h0, lane >> 1);
    float s1 = __shfl_sync(0xffffffffu, h1, lane >> 1);
    float hval = (lane & 1) ? s1 : s0;
    float xpv = 0.f;
#pragma unroll
    for (int i = 0; i < 32; i++)
        xpv += __shfl_sync(0xffffffffu, hval, i) * Wg[i * HDIM + lane];
    g_xp[(size_t)gw * HDIM + lane] = xpv;
    float a = xpv * asrc[lane];
    float b = xpv * adst[lane];
#pragma unroll
    for (int off = 16; off; off >>= 1) {
        a += __shfl_xor_sync(0xffffffffu, a, off);
        b += __shfl_xor_sync(0xffffffffu, b, off);
    }
    if (lane == 0) { g_asv[gw] = a; g_adv[gw] = b; }
}

// ---------------- GAT: two-pass softmax, lane-batched exp ----------------
__global__ void k_gat(const float* __restrict__ bgat) {
    int gw = (blockIdx.x * blockDim.x + threadIdx.x) >> 5;
    int lane = threadIdx.x & 31;
    if (gw >= NN) return;
    float advd = g_adv[gw];
    float xpd = g_xp[(size_t)gw * HDIM + lane];
    float es = g_asv[gw] + advd;
    es = es > 0.f ? es : 0.2f * es;
    int rs = g_rowptr[gw], re = g_rowptr[gw + 1];

    float m = es;
    for (int idx = rs + lane; idx < re; idx += 32) {
        int s = g_csr[idx].x;
        float sc = g_asv[s] + advd;
        sc = sc > 0.f ? sc : 0.2f * sc;
        m = fmaxf(m, sc);
    }
#pragma unroll
    for (int off = 16; off; off >>= 1)
        m = fmaxf(m, __shfl_xor_sync(0xffffffffu, m, off));

    float wself = __expf(es - m);
    float acc = wself * xpd;
    float ssum_part = (lane == 0) ? wself : 0.f;
    for (int base = rs; base < re; base += 32) {
        int idx2 = base + lane;
        float wl = 0.f; int sl = 0;
        if (idx2 < re) {
            sl = g_csr[idx2].x;
            float sc = g_asv[sl] + advd;
            sc = sc > 0.f ? sc : 0.2f * sc;
            wl = __expf(sc - m);
        }
        ssum_part += wl;
        int n = min(32, re - base);
        for (int i = 0; i < n; i++) {
            float wi = __shfl_sync(0xffffffffu, wl, i);
            int si = __shfl_sync(0xffffffffu, sl, i);
            acc += wi * g_xp[(size_t)si * HDIM + lane];
        }
    }
    float ssum = ssum_part;
#pragma unroll
    for (int off = 16; off; off >>= 1)
        ssum += __shfl_xor_sync(0xffffffffu, ssum, off);

    float h2 = acc / ssum + bgat[lane];
    h2 = fmaxf(h2, 0.f);
    float a = h2 * g_p[lane];
    float b = h2 * g_q[lane];
#pragma unroll
    for (int off = 16; off; off >>= 1) {
        a += __shfl_xor_sync(0xffffffffu, a, off);
        b += __shfl_xor_sync(0xffffffffu, b, off);
    }
    if (lane == 0) { g_u[gw] = a + g_cuv[0]; g_v[gw] = b + g_cuv[1]; }
}

__global__ void k_out(const int* __restrict__ ei, const float* __restrict__ bcls,
                      float* __restrict__ out) {
    int e = blockIdx.x * blockDim.x + threadIdx.x;
    if (e >= EE) return;
    out[e] = g_u[ei[e]] + g_v[ei[EE + e]] + bcls[0];
}

// ---------------- launch (chunk widths {4,8,8,12}; b2=NULL first step) ----------------
extern "C" void kernel_launch(void* const* d_in, const int* in_sizes, int n_in,
                              void* d_out, int out_size) {
    const float* x    = (const float*)d_in[0];
    const int*   ei   = (const int*)d_in[1];
    const float* Wxz  = (const float*)d_in[2];
    const float* Wxh  = (const float*)d_in[6];
    const float* bxz  = (const float*)d_in[8];
    const float* bhz  = (const float*)d_in[9];
    const float* bxh  = (const float*)d_in[12];
    const float* bhh  = (const float*)d_in[13];
    const float* Wgat = (const float*)d_in[14];
    const float* asrc = (const float*)d_in[15];
    const float* adst = (const float*)d_in[16];
    const float* bgat = (const float*)d_in[17];
    const float* Wemb = (const float*)d_in[18];
    const float* bemb = (const float*)d_in[19];
    const float* Wcls = (const float*)d_in[20];
    const float* bcls = (const float*)d_in[21];
    float* out = (float*)d_out;

    static cudaStream_t s2 = nullptr;
    static cudaEvent_t ev_fork = nullptr, ev_chunk[4] = {nullptr, nullptr, nullptr, nullptr};
    static float* pB = nullptr;
    static float* pY = nullptr;
    if (s2 == nullptr) {
        cudaStreamCreateWithFlags(&s2, cudaStreamNonBlocking);
        cudaEventCreateWithFlags(&ev_fork, cudaEventDisableTiming);
        for (int i = 0; i < 4; i++)
            cudaEventCreateWithFlags(&ev_chunk[i], cudaEventDisableTiming);
        cudaGetSymbolAddress((void**)&pB, g_B);
        cudaGetSymbolAddress((void**)&pY, g_Y);
    }
    const size_t slab = (size_t)NN * HD2;
    float* buf[3] = { pB, pB + slab, pB + 2 * slab };
    float* Y31 = pY + (size_t)31 * slab;

    const int EB = (EE + 255) / 256;
    const int NB = (NN * 32 + 255) / 256;

    cudaEventRecord(ev_fork, 0);
    cudaStreamWaitEvent(s2, ev_fork, 0);

    // s2: x conversion once, then weight prep + GEMM in 4 chunks {4,8,8,12}, descending cb
    const int cb_base_arr[4] = {28, 20, 12, 0};
    const int cb_w_arr[4]    = {4,  8,  8,  12};
    k_prep_x<<<(NROWS * 128 + 255) / 256, 256, 0, s2>>>(x);
    for (int ch = 0; ch < 4; ch++) {
        int base = cb_base_arr[ch], w = cb_w_arr[ch];
        k_prep_wbf<<<(w * 64 * 128 + 255) / 256, 256, 0, s2>>>(Wxz, Wxh, base * 64, w * 64);
        k_gemm<<<dim3(157, w), 256, 0, s2>>>(base);
        cudaEventRecord(ev_chunk[ch], s2);
    }

    // main stream: CSR build + small preps (overlaps chunk 0)
    k_zero<<<160, 256>>>();
    k_hist<<<EB, 256>>>(ei);
    k_scan<<<1, 1024>>>();
    k_scatter<<<EB, 256>>>(ei);
    k_prep_pq<<<1, 64>>>(Wemb, bemb, Wcls);

    // step chain: b31 = Y[31]; first step has b2 = NULL (b32 = 0)
    // chunk0 covers cb 28-31, ch1 20-27, ch2 12-19, ch3 0-11
    float* b1 = Y31;
    float* b2 = nullptr;
    int idx = 0;
    cudaStreamWaitEvent(0, ev_chunk[0], 0);
    for (int k = KORD - 2; k >= 1; k--) {
        if (k == 27) cudaStreamWaitEvent(0, ev_chunk[1], 0);
        if (k == 19) cudaStreamWaitEvent(0, ev_chunk[2], 0);
        if (k == 11) cudaStreamWaitEvent(0, ev_chunk[3], 0);
        float* bn = buf[idx];
        k_cheb_step<<<NB, 256>>>(k, bn, b1, b2);
        b2 = b1; b1 = bn; idx = (idx + 1) % 3;
    }
    k_cheb_final_xp<<<NB, 256>>>(b1, b2, bxz, bhz, bxh, bhh, Wgat, asrc, adst);
    k_gat<<<NB, 256>>>(bgat);
    k_out<<<EB, 256>>>(ei, bcls, out);
}